// round 1
// baseline (speedup 1.0000x reference)
#include <cuda_runtime.h>

#define BB 64
#define NN 64
#define TT 16
#define DD 512
#define RR (BB*NN)          // 4096 rows (b,m)
#define THR2 (150.0f*150.0f)

// ---------------- scratch (device globals, no allocation) ----------------
__device__ float g_AnT[BB*NN*NN];   // AnT[b][m][n] = A_norm[b][n][m]
__device__ float g_agg[RR*DD];      // aggregation output  [r][c]
__device__ float g_z[RR*DD];        // pre-BN GEMM output  [r][o]
__device__ float g_h[RR*DD];        // layer-1 activations [r][c]
__device__ float g_psum[64*DD];     // BN partial sums
__device__ float g_psq[64*DD];      // BN partial sums of squares
__device__ float g_scale[DD];
__device__ float g_shift[DD];

// ---------------- full tensor copy: out = person_features ----------------
__global__ void k_copy(const float4* __restrict__ src, float4* __restrict__ dst) {
    int i = blockIdx.x * blockDim.x + threadIdx.x;   // grid covers exactly
    dst[i] = src[i];
}

// ---------------- adjacency + row-normalize (transposed) ----------------
// A[n][m] = (n==m) || dist2(n,m) < 150^2 ; deg[n] = row sum
// g_AnT[b][m][n] = A[n][m] / (deg[n] + 1e-6)
__global__ void k_adj(const float* __restrict__ bb) {
    __shared__ float cx[NN], cy[NN], invdeg[NN];
    int b = blockIdx.x;
    int t = threadIdx.x;                 // 256 threads
    if (t < NN) {
        const float* p = bb + (b*NN + t)*4;
        cx[t] = p[0] + 0.5f*p[2];
        cy[t] = p[1] + 0.5f*p[3];
    }
    __syncthreads();
    if (t < NN) {
        float x0 = cx[t], y0 = cy[t];
        int cnt = 0;
        #pragma unroll 8
        for (int m = 0; m < NN; m++) {
            float dx = x0 - cx[m], dy = y0 - cy[m];
            if (m != t && dx*dx + dy*dy < THR2) cnt++;
        }
        invdeg[t] = 1.0f / ((float)(cnt + 1) + 1e-6f);
    }
    __syncthreads();
    for (int e = t; e < NN*NN; e += 256) {
        int m = e >> 6, n = e & 63;
        float dx = cx[n]-cx[m], dy = cy[n]-cy[m];
        float d2 = dx*dx + dy*dy;
        float v = (n == m || d2 < THR2) ? invdeg[n] : 0.0f;
        g_AnT[b*NN*NN + e] = v;
    }
}

// ---------------- graph aggregation ----------------
// g_agg[b][m][c] = sum_n AnT[b][m][n] * x[b][n][c]
// x source: external (person_features slice) or g_h (layer 2)
// grid (64 b, 8 c-chunks of 64), 256 threads
__global__ void __launch_bounds__(256) k_agg(const float* __restrict__ xext, int useExt,
                                             int bStride, int nStride, int off) {
    __shared__ float Asm[NN*NN];      // [m][n]
    __shared__ float Xs[NN][68];      // [n][cc], padded
    const float* x = useExt ? xext : g_h;
    int b = blockIdx.x;
    int cBase = blockIdx.y * 64;
    int t = threadIdx.x;

    const float4* ap = (const float4*)(g_AnT + b*NN*NN);
    float4* asp = (float4*)Asm;
    #pragma unroll
    for (int i = 0; i < 4; i++) asp[t + 256*i] = ap[t + 256*i];

    #pragma unroll
    for (int i = 0; i < 4; i++) {
        int e  = t + 256*i;            // 0..1023
        int n  = e >> 4;
        int cg = (e & 15) * 4;
        float4 v = *(const float4*)&x[b*bStride + n*nStride + off + cBase + cg];
        *(float4*)&Xs[n][cg] = v;
    }
    __syncthreads();

    int ty = t >> 4, tx = t & 15;
    int m0 = ty * 4, c0 = tx * 4;
    float acc[4][4] = {};
    for (int n = 0; n < NN; n++) {
        float a0 = Asm[(m0+0)*NN + n];
        float a1 = Asm[(m0+1)*NN + n];
        float a2 = Asm[(m0+2)*NN + n];
        float a3 = Asm[(m0+3)*NN + n];
        float4 xv = *(const float4*)&Xs[n][c0];
        acc[0][0] += a0*xv.x; acc[0][1] += a0*xv.y; acc[0][2] += a0*xv.z; acc[0][3] += a0*xv.w;
        acc[1][0] += a1*xv.x; acc[1][1] += a1*xv.y; acc[1][2] += a1*xv.z; acc[1][3] += a1*xv.w;
        acc[2][0] += a2*xv.x; acc[2][1] += a2*xv.y; acc[2][2] += a2*xv.z; acc[2][3] += a2*xv.w;
        acc[3][0] += a3*xv.x; acc[3][1] += a3*xv.y; acc[3][2] += a3*xv.z; acc[3][3] += a3*xv.w;
    }
    #pragma unroll
    for (int i = 0; i < 4; i++) {
        float4 v = make_float4(acc[i][0], acc[i][1], acc[i][2], acc[i][3]);
        *(float4*)&g_agg[(b*NN + m0 + i)*DD + cBase + c0] = v;
    }
}

// ---------------- dense GEMM: g_z[r][o] = sum_c g_agg[r][c]*W[o][c] + bias[o] ----------------
// grid (64 r-tiles, 8 o-tiles), 256 threads, 64x64 tile, BK=16, 4x4 per thread
__global__ void __launch_bounds__(256) k_gemm(const float* __restrict__ W,
                                              const float* __restrict__ bias) {
    __shared__ float As[16][68];      // As[k][r]
    __shared__ float Bs[16][68];      // Bs[k][o]
    int rBase = blockIdx.x * 64;
    int oBase = blockIdx.y * 64;
    int t  = threadIdx.x;
    int lr = t >> 2;
    int lk = (t & 3) * 4;
    int ty = t >> 4, tx = t & 15;
    int r0 = ty * 4, c0 = tx * 4;
    float acc[4][4] = {};

    for (int k0 = 0; k0 < DD; k0 += 16) {
        float4 av = *(const float4*)&g_agg[(rBase+lr)*DD + k0 + lk];
        float4 bv = *(const float4*)&W[(oBase+lr)*DD + k0 + lk];
        As[lk+0][lr]=av.x; As[lk+1][lr]=av.y; As[lk+2][lr]=av.z; As[lk+3][lr]=av.w;
        Bs[lk+0][lr]=bv.x; Bs[lk+1][lr]=bv.y; Bs[lk+2][lr]=bv.z; Bs[lk+3][lr]=bv.w;
        __syncthreads();
        #pragma unroll
        for (int k = 0; k < 16; k++) {
            float4 a  = *(const float4*)&As[k][r0];
            float4 bq = *(const float4*)&Bs[k][c0];
            acc[0][0] += a.x*bq.x; acc[0][1] += a.x*bq.y; acc[0][2] += a.x*bq.z; acc[0][3] += a.x*bq.w;
            acc[1][0] += a.y*bq.x; acc[1][1] += a.y*bq.y; acc[1][2] += a.y*bq.z; acc[1][3] += a.y*bq.w;
            acc[2][0] += a.z*bq.x; acc[2][1] += a.z*bq.y; acc[2][2] += a.z*bq.z; acc[2][3] += a.z*bq.w;
            acc[3][0] += a.w*bq.x; acc[3][1] += a.w*bq.y; acc[3][2] += a.w*bq.z; acc[3][3] += a.w*bq.w;
        }
        __syncthreads();
    }

    float4 b4 = *(const float4*)&bias[oBase + c0];
    #pragma unroll
    for (int i = 0; i < 4; i++) {
        float4 v = make_float4(acc[i][0]+b4.x, acc[i][1]+b4.y, acc[i][2]+b4.z, acc[i][3]+b4.w);
        *(float4*)&g_z[(rBase + r0 + i)*DD + oBase + c0] = v;
    }
}

// ---------------- BN stats: deterministic 2-stage reduction ----------------
__global__ void k_stats() {
    int rb = blockIdx.x;          // 64 blocks, 64 rows each
    int o  = threadIdx.x;         // 512 threads
    float s = 0.0f, q = 0.0f;
    #pragma unroll 8
    for (int i = 0; i < 64; i++) {
        float v = g_z[(rb*64 + i)*DD + o];
        s += v; q += v*v;
    }
    g_psum[rb*DD + o] = s;
    g_psq [rb*DD + o] = q;
}

__global__ void k_finalize(const float* __restrict__ gma, const float* __restrict__ bta) {
    int o = threadIdx.x;          // 512 threads, 1 block
    float s = 0.0f, q = 0.0f;
    #pragma unroll 8
    for (int i = 0; i < 64; i++) { s += g_psum[i*DD + o]; q += g_psq[i*DD + o]; }
    float mean = s * (1.0f/4096.0f);
    float var  = q * (1.0f/4096.0f) - mean*mean;
    float inv  = rsqrtf(var + 1e-5f);
    float sc   = gma[o] * inv;
    g_scale[o] = sc;
    g_shift[o] = bta[o] - mean * sc;
}

// ---------------- BN apply + ReLU ----------------
// toSlice=0: write g_h ; toSlice=1: write out[:, :, 15, :]
__global__ void k_apply(float* __restrict__ outp, int toSlice) {
    int i  = blockIdx.x * blockDim.x + threadIdx.x;  // float4 index, 524288 total
    int r  = i >> 7;               // DD/4 = 128 per row
    int cw = i & 127;
    float4 z  = ((const float4*)g_z)[i];
    float4 sc = ((const float4*)g_scale)[cw];
    float4 sh = ((const float4*)g_shift)[cw];
    float4 h;
    h.x = fmaxf(fmaf(z.x, sc.x, sh.x), 0.0f);
    h.y = fmaxf(fmaf(z.y, sc.y, sh.y), 0.0f);
    h.z = fmaxf(fmaf(z.z, sc.z, sh.z), 0.0f);
    h.w = fmaxf(fmaf(z.w, sc.w, sh.w), 0.0f);
    if (toSlice) *(float4*)&outp[r*(TT*DD) + 15*DD + cw*4] = h;
    else         ((float4*)g_h)[i] = h;
}

// ---------------- launcher ----------------
extern "C" void kernel_launch(void* const* d_in, const int* in_sizes, int n_in,
                              void* d_out, int out_size) {
    const float* pf  = (const float*)d_in[0];
    const float* bbx = (const float*)d_in[1];
    const float* w1  = (const float*)d_in[2];
    const float* b1  = (const float*)d_in[3];
    const float* g1  = (const float*)d_in[4];
    const float* be1 = (const float*)d_in[5];
    const float* w2  = (const float*)d_in[6];
    const float* b2  = (const float*)d_in[7];
    const float* g2  = (const float*)d_in[8];
    const float* be2 = (const float*)d_in[9];
    float* out = (float*)d_out;

    // full copy: 64*64*16*512 floats = 8388608 float4
    k_copy<<<32768, 256>>>((const float4*)pf, (float4*)out);
    k_adj<<<64, 256>>>(bbx);

    // layer 1 (x = pf[:, :, 15, :])
    k_agg<<<dim3(64, 8), 256>>>(pf, 1, NN*TT*DD, TT*DD, 15*DD);
    k_gemm<<<dim3(64, 8), 256>>>(w1, b1);
    k_stats<<<64, 512>>>();
    k_finalize<<<1, 512>>>(g1, be1);
    k_apply<<<2048, 256>>>(nullptr, 0);

    // layer 2 (x = g_h)
    k_agg<<<dim3(64, 8), 256>>>(nullptr, 0, NN*DD, DD, 0);
    k_gemm<<<dim3(64, 8), 256>>>(w2, b2);
    k_stats<<<64, 512>>>();
    k_finalize<<<1, 512>>>(g2, be2);
    k_apply<<<2048, 256>>>(out, 1);
}

// round 3
// speedup vs baseline: 1.3802x; 1.3802x over previous
#include <cuda_runtime.h>
#include <cstdint>

#define BB 64
#define NN 64
#define TT 16
#define DD 512
#define RR (BB*NN)          // 4096 rows (b,m)
#define THR2 (150.0f*150.0f)

// ---------------- scratch (device globals, no allocation) ----------------
__device__ float g_AnT[BB*NN*NN];   // AnT[b][m][n] = A_norm[b][n][m]
__device__ float g_agg[RR*DD];      // aggregation output  [r][c]
__device__ float g_z[RR*DD];        // pre-BN GEMM output  [r][o]
__device__ float g_h[RR*DD];        // layer-1 activations [r][c]
__device__ float g_psum[64*DD];     // BN partial sums
__device__ float g_psq[64*DD];      // BN partial sums of squares
__device__ float g_scale[DD];
__device__ float g_shift[DD];

// ---------------- full tensor copy: out = person_features ----------------
__global__ void k_copy(const float4* __restrict__ src, float4* __restrict__ dst) {
    int i = blockIdx.x * blockDim.x + threadIdx.x;
    dst[i] = src[i];
}

// ---------------- adjacency + row-normalize (transposed) ----------------
__global__ void k_adj(const float* __restrict__ bb) {
    __shared__ float cx[NN], cy[NN], invdeg[NN];
    int b = blockIdx.x;
    int t = threadIdx.x;
    if (t < NN) {
        const float* p = bb + (b*NN + t)*4;
        cx[t] = p[0] + 0.5f*p[2];
        cy[t] = p[1] + 0.5f*p[3];
    }
    __syncthreads();
    if (t < NN) {
        float x0 = cx[t], y0 = cy[t];
        int cnt = 0;
        #pragma unroll 8
        for (int m = 0; m < NN; m++) {
            float dx = x0 - cx[m], dy = y0 - cy[m];
            if (m != t && dx*dx + dy*dy < THR2) cnt++;
        }
        invdeg[t] = 1.0f / ((float)(cnt + 1) + 1e-6f);
    }
    __syncthreads();
    for (int e = t; e < NN*NN; e += 256) {
        int m = e >> 6, n = e & 63;
        float dx = cx[n]-cx[m], dy = cy[n]-cy[m];
        float d2 = dx*dx + dy*dy;
        float v = (n == m || d2 < THR2) ? invdeg[n] : 0.0f;
        g_AnT[b*NN*NN + e] = v;
    }
}

// ---------------- graph aggregation (SIMT, small) ----------------
__global__ void __launch_bounds__(256) k_agg(const float* __restrict__ xext, int useExt,
                                             int bStride, int nStride, int off) {
    __shared__ float Asm[NN*NN];
    __shared__ float Xs[NN][68];
    const float* x = useExt ? xext : g_h;
    int b = blockIdx.x;
    int cBase = blockIdx.y * 64;
    int t = threadIdx.x;

    const float4* ap = (const float4*)(g_AnT + b*NN*NN);
    float4* asp = (float4*)Asm;
    #pragma unroll
    for (int i = 0; i < 4; i++) asp[t + 256*i] = ap[t + 256*i];

    #pragma unroll
    for (int i = 0; i < 4; i++) {
        int e  = t + 256*i;
        int n  = e >> 4;
        int cg = (e & 15) * 4;
        float4 v = *(const float4*)&x[b*bStride + n*nStride + off + cBase + cg];
        *(float4*)&Xs[n][cg] = v;
    }
    __syncthreads();

    int ty = t >> 4, tx = t & 15;
    int m0 = ty * 4, c0 = tx * 4;
    float acc[4][4] = {};
    for (int n = 0; n < NN; n++) {
        float a0 = Asm[(m0+0)*NN + n];
        float a1 = Asm[(m0+1)*NN + n];
        float a2 = Asm[(m0+2)*NN + n];
        float a3 = Asm[(m0+3)*NN + n];
        float4 xv = *(const float4*)&Xs[n][c0];
        acc[0][0] += a0*xv.x; acc[0][1] += a0*xv.y; acc[0][2] += a0*xv.z; acc[0][3] += a0*xv.w;
        acc[1][0] += a1*xv.x; acc[1][1] += a1*xv.y; acc[1][2] += a1*xv.z; acc[1][3] += a1*xv.w;
        acc[2][0] += a2*xv.x; acc[2][1] += a2*xv.y; acc[2][2] += a2*xv.z; acc[2][3] += a2*xv.w;
        acc[3][0] += a3*xv.x; acc[3][1] += a3*xv.y; acc[3][2] += a3*xv.z; acc[3][3] += a3*xv.w;
    }
    #pragma unroll
    for (int i = 0; i < 4; i++) {
        float4 v = make_float4(acc[i][0], acc[i][1], acc[i][2], acc[i][3]);
        *(float4*)&g_agg[(b*NN + m0 + i)*DD + cBase + c0] = v;
    }
}

// ---------------- tf32 mma.sync GEMM ----------------
// g_z[r][o] = sum_c g_agg[r][c]*W[o][c] + bias[o]
// Block 128x128, BK=32, 8 warps (2M x 4N), warp tile 64x32 via m16n8k8.
// Smem layouts (fragment-order, per buffer, in floats):
//   A: [mt8][ks4][lane32][4]  (16KB)   a_j = A[mt*16 + (lane/4) + 8*(j&1)][ks*8 + (lane%4) + 4*(j>>1)]
//   B: [nt16][ks4][lane32][2] (16KB)   b_j = W[nt*8 + lane/4][ks*8 + (lane%4) + 4*j]
#define ABUF(b) ((b)*4096)
#define BBUF(b) (8192 + (b)*4096)
#define GEMM_SMEM (16384*4)

__device__ __forceinline__ uint32_t to_tf32(float x) {
    uint32_t y;
    asm("cvt.rna.tf32.f32 %0, %1;" : "=r"(y) : "f"(x));
    return y;
}
__device__ __forceinline__ void mma_tf32(float* c, const uint32_t* a, const uint32_t* b) {
    asm volatile(
        "mma.sync.aligned.m16n8k8.row.col.f32.tf32.tf32.f32 "
        "{%0,%1,%2,%3}, {%4,%5,%6,%7}, {%8,%9}, {%0,%1,%2,%3};"
        : "+f"(c[0]), "+f"(c[1]), "+f"(c[2]), "+f"(c[3])
        : "r"(a[0]), "r"(a[1]), "r"(a[2]), "r"(a[3]), "r"(b[0]), "r"(b[1]));
}

__global__ void __launch_bounds__(256) k_gemm_mma(const float* __restrict__ W,
                                                  const float* __restrict__ bias) {
    extern __shared__ float sm[];
    int t = threadIdx.x;
    int lane = t & 31;
    int wid = t >> 5;
    int wm = wid >> 2, wn = wid & 3;          // warp 64-row half, 32-col quarter
    int rBase = blockIdx.x * 128;
    int oBase = blockIdx.y * 128;
    const float* A = g_agg;

    float acc[4][4][4];
    #pragma unroll
    for (int mt = 0; mt < 4; mt++)
        #pragma unroll
        for (int nt = 0; nt < 4; nt++)
            #pragma unroll
            for (int j = 0; j < 4; j++) acc[mt][nt][j] = 0.0f;

    // ---- fill chunk 0 into buffer 0 ----
    #pragma unroll
    for (int i = 0; i < 4; i++) {
        int idx = t + 256*i;
        int row = idx >> 3, cg = idx & 7;
        float4 av = *(const float4*)&A[(rBase+row)*DD + 0 + cg*4];
        float4 bv = *(const float4*)&W[(oBase+row)*DD + 0 + cg*4];
        int ks = cg >> 1, half = cg & 1;
        {   // A scatter: comp = hi + 2*half, lane = r8*4 + j
            int mt = row >> 4, rin = row & 15, r8 = rin & 7, hi = rin >> 3;
            float* ab = &sm[ABUF(0) + ((mt*4 + ks)*32)*4 + (hi + 2*half)];
            ab[(r8*4+0)*4] = __uint_as_float(to_tf32(av.x));
            ab[(r8*4+1)*4] = __uint_as_float(to_tf32(av.y));
            ab[(r8*4+2)*4] = __uint_as_float(to_tf32(av.z));
            ab[(r8*4+3)*4] = __uint_as_float(to_tf32(av.w));
        }
        {   // B scatter: comp = half, lane = nin*4 + j
            int nt = row >> 3, nin = row & 7;
            float* bb = &sm[BBUF(0) + ((nt*4 + ks)*32)*2 + half];
            bb[(nin*4+0)*2] = __uint_as_float(to_tf32(bv.x));
            bb[(nin*4+1)*2] = __uint_as_float(to_tf32(bv.y));
            bb[(nin*4+2)*2] = __uint_as_float(to_tf32(bv.z));
            bb[(nin*4+3)*2] = __uint_as_float(to_tf32(bv.w));
        }
    }
    __syncthreads();

    #pragma unroll 1
    for (int it = 0; it < 16; it++) {
        int cur = it & 1;
        // ---- prefetch next chunk into other buffer (overlaps with HMMA below) ----
        if (it + 1 < 16) {
            int nb = 1 - cur;
            int k0 = (it + 1) * 32;
            #pragma unroll
            for (int i = 0; i < 4; i++) {
                int idx = t + 256*i;
                int row = idx >> 3, cg = idx & 7;
                float4 av = *(const float4*)&A[(rBase+row)*DD + k0 + cg*4];
                float4 bv = *(const float4*)&W[(oBase+row)*DD + k0 + cg*4];
                int ks = cg >> 1, half = cg & 1;
                {
                    int mt = row >> 4, rin = row & 15, r8 = rin & 7, hi = rin >> 3;
                    float* ab = &sm[ABUF(nb) + ((mt*4 + ks)*32)*4 + (hi + 2*half)];
                    ab[(r8*4+0)*4] = __uint_as_float(to_tf32(av.x));
                    ab[(r8*4+1)*4] = __uint_as_float(to_tf32(av.y));
                    ab[(r8*4+2)*4] = __uint_as_float(to_tf32(av.z));
                    ab[(r8*4+3)*4] = __uint_as_float(to_tf32(av.w));
                }
                {
                    int nt = row >> 3, nin = row & 7;
                    float* bb = &sm[BBUF(nb) + ((nt*4 + ks)*32)*2 + half];
                    bb[(nin*4+0)*2] = __uint_as_float(to_tf32(bv.x));
                    bb[(nin*4+1)*2] = __uint_as_float(to_tf32(bv.y));
                    bb[(nin*4+2)*2] = __uint_as_float(to_tf32(bv.z));
                    bb[(nin*4+3)*2] = __uint_as_float(to_tf32(bv.w));
                }
            }
        }
        // ---- compute on current buffer ----
        #pragma unroll
        for (int ks = 0; ks < 4; ks++) {
            uint32_t af[4][4], bf[4][2];
            #pragma unroll
            for (int mt = 0; mt < 4; mt++) {
                const float4 v = *(const float4*)&sm[ABUF(cur) + (((wm*4+mt)*4 + ks)*32 + lane)*4];
                af[mt][0] = __float_as_uint(v.x); af[mt][1] = __float_as_uint(v.y);
                af[mt][2] = __float_as_uint(v.z); af[mt][3] = __float_as_uint(v.w);
            }
            #pragma unroll
            for (int nt = 0; nt < 4; nt++) {
                const float2 v = *(const float2*)&sm[BBUF(cur) + (((wn*4+nt)*4 + ks)*32 + lane)*2];
                bf[nt][0] = __float_as_uint(v.x); bf[nt][1] = __float_as_uint(v.y);
            }
            #pragma unroll
            for (int mt = 0; mt < 4; mt++)
                #pragma unroll
                for (int nt = 0; nt < 4; nt++)
                    mma_tf32(acc[mt][nt], af[mt], bf[nt]);
        }
        __syncthreads();
    }

    // ---- epilogue: bias add, write g_z ----
    #pragma unroll
    for (int nt = 0; nt < 4; nt++) {
        int col = oBase + wn*32 + nt*8 + (lane & 3)*2;
        float2 bv = *(const float2*)&bias[col];
        #pragma unroll
        for (int mt = 0; mt < 4; mt++) {
            int row0 = rBase + wm*64 + mt*16 + (lane >> 2);
            float2 v0 = make_float2(acc[mt][nt][0] + bv.x, acc[mt][nt][1] + bv.y);
            float2 v1 = make_float2(acc[mt][nt][2] + bv.x, acc[mt][nt][3] + bv.y);
            *(float2*)&g_z[row0*DD + col]     = v0;
            *(float2*)&g_z[(row0+8)*DD + col] = v1;
        }
    }
}

// ---------------- BN stats: deterministic 2-stage reduction ----------------
__global__ void k_stats() {
    int rb = blockIdx.x;
    int o  = threadIdx.x;
    float s = 0.0f, q = 0.0f;
    #pragma unroll 8
    for (int i = 0; i < 64; i++) {
        float v = g_z[(rb*64 + i)*DD + o];
        s += v; q += v*v;
    }
    g_psum[rb*DD + o] = s;
    g_psq [rb*DD + o] = q;
}

__global__ void k_finalize(const float* __restrict__ gma, const float* __restrict__ bta) {
    int o = threadIdx.x;
    float s = 0.0f, q = 0.0f;
    #pragma unroll 8
    for (int i = 0; i < 64; i++) { s += g_psum[i*DD + o]; q += g_psq[i*DD + o]; }
    float mean = s * (1.0f/4096.0f);
    float var  = q * (1.0f/4096.0f) - mean*mean;
    float inv  = rsqrtf(var + 1e-5f);
    float sc   = gma[o] * inv;
    g_scale[o] = sc;
    g_shift[o] = bta[o] - mean * sc;
}

// ---------------- BN apply + ReLU ----------------
__global__ void k_apply(float* __restrict__ outp, int toSlice) {
    int i  = blockIdx.x * blockDim.x + threadIdx.x;
    int r  = i >> 7;
    int cw = i & 127;
    float4 z  = ((const float4*)g_z)[i];
    float4 sc = ((const float4*)g_scale)[cw];
    float4 sh = ((const float4*)g_shift)[cw];
    float4 h;
    h.x = fmaxf(fmaf(z.x, sc.x, sh.x), 0.0f);
    h.y = fmaxf(fmaf(z.y, sc.y, sh.y), 0.0f);
    h.z = fmaxf(fmaf(z.z, sc.z, sh.z), 0.0f);
    h.w = fmaxf(fmaf(z.w, sc.w, sh.w), 0.0f);
    if (toSlice) *(float4*)&outp[r*(TT*DD) + 15*DD + cw*4] = h;
    else         ((float4*)g_h)[i] = h;
}

// ---------------- launcher ----------------
extern "C" void kernel_launch(void* const* d_in, const int* in_sizes, int n_in,
                              void* d_out, int out_size) {
    const float* pf  = (const float*)d_in[0];
    const float* bbx = (const float*)d_in[1];
    const float* w1  = (const float*)d_in[2];
    const float* b1  = (const float*)d_in[3];
    const float* g1  = (const float*)d_in[4];
    const float* be1 = (const float*)d_in[5];
    const float* w2  = (const float*)d_in[6];
    const float* b2  = (const float*)d_in[7];
    const float* g2  = (const float*)d_in[8];
    const float* be2 = (const float*)d_in[9];
    float* out = (float*)d_out;

    static int s_attr_done = 0;
    if (!s_attr_done) {
        cudaFuncSetAttribute(k_gemm_mma, cudaFuncAttributeMaxDynamicSharedMemorySize, GEMM_SMEM);
        s_attr_done = 1;
    }

    k_copy<<<32768, 256>>>((const float4*)pf, (float4*)out);
    k_adj<<<64, 256>>>(bbx);

    // layer 1 (x = pf[:, :, 15, :])
    k_agg<<<dim3(64, 8), 256>>>(pf, 1, NN*TT*DD, TT*DD, 15*DD);
    k_gemm_mma<<<dim3(32, 4), 256, GEMM_SMEM>>>(w1, b1);
    k_stats<<<64, 512>>>();
    k_finalize<<<1, 512>>>(g1, be1);
    k_apply<<<2048, 256>>>(nullptr, 0);

    // layer 2 (x = g_h)
    k_agg<<<dim3(64, 8), 256>>>(nullptr, 0, NN*DD, DD, 0);
    k_gemm_mma<<<dim3(32, 4), 256, GEMM_SMEM>>>(w2, b2);
    k_stats<<<64, 512>>>();
    k_finalize<<<1, 512>>>(g2, be2);
    k_apply<<<2048, 256>>>(out, 1);
}

// round 7
// speedup vs baseline: 1.5470x; 1.1208x over previous
#include <cuda_runtime.h>
#include <cstdint>

#define BB 64
#define NN 64
#define TT 16
#define DD 512
#define RR (BB*NN)          // 4096 rows (b,m)
#define THR2 (150.0f*150.0f)

// ---------------- scratch (device globals, no allocation) ----------------
__device__ float g_AnT[BB*NN*NN];   // AnT[b][m][n] = A_norm[b][n][m]
__device__ float g_agg[RR*DD];      // aggregation output  [r][c]
__device__ float g_z[RR*DD];        // pre-BN GEMM output  [r][o]
__device__ float g_psum[64*DD];     // BN partial sums
__device__ float g_psq[64*DD];      // BN partial sums of squares
__device__ float g_scale[DD];
__device__ float g_shift[DD];

// ---------------- warmup (forces stream resource materialization pre-main) --
__global__ void k_warm() {}

// ---------------- side-stream copy: out[:, :, t!=15, :] = pf ----------------
// grid (4096, 15), 128 threads; one float4 per thread
__global__ void k_copy15(const float4* __restrict__ src, float4* __restrict__ dst) {
    int i = (blockIdx.x * 16 + blockIdx.y) * 128 + threadIdx.x;
    dst[i] = src[i];
}

// ---------------- adjacency + row-normalize (transposed) ----------------
__global__ void k_adj(const float* __restrict__ bb) {
    __shared__ float cx[NN], cy[NN], invdeg[NN];
    int b = blockIdx.x;
    int t = threadIdx.x;
    if (t < NN) {
        const float* p = bb + (b*NN + t)*4;
        cx[t] = p[0] + 0.5f*p[2];
        cy[t] = p[1] + 0.5f*p[3];
    }
    __syncthreads();
    if (t < NN) {
        float x0 = cx[t], y0 = cy[t];
        int cnt = 0;
        #pragma unroll 8
        for (int m = 0; m < NN; m++) {
            float dx = x0 - cx[m], dy = y0 - cy[m];
            if (m != t && dx*dx + dy*dy < THR2) cnt++;
        }
        invdeg[t] = 1.0f / ((float)(cnt + 1) + 1e-6f);
    }
    __syncthreads();
    for (int e = t; e < NN*NN; e += 256) {
        int m = e >> 6, n = e & 63;
        float dx = cx[n]-cx[m], dy = cy[n]-cy[m];
        float d2 = dx*dx + dy*dy;
        float v = (n == m || d2 < THR2) ? invdeg[n] : 0.0f;
        g_AnT[b*NN*NN + e] = v;
    }
}

// ---------------- graph aggregation ----------------
// mode 0: x[n][c] = pf[b][n][15][c]
// mode 1: x[n][c] = relu(g_z[b*NN+n][c]*scale[c] + shift[c])  (fused layer-1 BN apply)
__global__ void __launch_bounds__(256) k_agg(const float* __restrict__ pf, int mode) {
    __shared__ float Asm[NN*NN];
    __shared__ float Xs[NN][68];
    int b = blockIdx.x;
    int cBase = blockIdx.y * 64;
    int t = threadIdx.x;

    const float4* ap = (const float4*)(g_AnT + b*NN*NN);
    float4* asp = (float4*)Asm;
    #pragma unroll
    for (int i = 0; i < 4; i++) asp[t + 256*i] = ap[t + 256*i];

    #pragma unroll
    for (int i = 0; i < 4; i++) {
        int e  = t + 256*i;
        int n  = e >> 4;
        int cg = (e & 15) * 4;
        float4 v;
        if (mode == 0) {
            v = *(const float4*)&pf[((b*NN + n)*TT + 15)*DD + cBase + cg];
        } else {
            float4 z  = *(const float4*)&g_z[(b*NN + n)*DD + cBase + cg];
            float4 sc = *(const float4*)&g_scale[cBase + cg];
            float4 sh = *(const float4*)&g_shift[cBase + cg];
            v.x = fmaxf(fmaf(z.x, sc.x, sh.x), 0.0f);
            v.y = fmaxf(fmaf(z.y, sc.y, sh.y), 0.0f);
            v.z = fmaxf(fmaf(z.z, sc.z, sh.z), 0.0f);
            v.w = fmaxf(fmaf(z.w, sc.w, sh.w), 0.0f);
        }
        *(float4*)&Xs[n][cg] = v;
    }
    __syncthreads();

    int ty = t >> 4, tx = t & 15;
    int m0 = ty * 4, c0 = tx * 4;
    float acc[4][4] = {};
    for (int n = 0; n < NN; n++) {
        float a0 = Asm[(m0+0)*NN + n];
        float a1 = Asm[(m0+1)*NN + n];
        float a2 = Asm[(m0+2)*NN + n];
        float a3 = Asm[(m0+3)*NN + n];
        float4 xv = *(const float4*)&Xs[n][c0];
        acc[0][0] += a0*xv.x; acc[0][1] += a0*xv.y; acc[0][2] += a0*xv.z; acc[0][3] += a0*xv.w;
        acc[1][0] += a1*xv.x; acc[1][1] += a1*xv.y; acc[1][2] += a1*xv.z; acc[1][3] += a1*xv.w;
        acc[2][0] += a2*xv.x; acc[2][1] += a2*xv.y; acc[2][2] += a2*xv.z; acc[2][3] += a2*xv.w;
        acc[3][0] += a3*xv.x; acc[3][1] += a3*xv.y; acc[3][2] += a3*xv.z; acc[3][3] += a3*xv.w;
    }
    #pragma unroll
    for (int i = 0; i < 4; i++) {
        float4 v = make_float4(acc[i][0], acc[i][1], acc[i][2], acc[i][3]);
        *(float4*)&g_agg[(b*NN + m0 + i)*DD + cBase + c0] = v;
    }
}

// ---------------- tf32 mma.sync GEMM ----------------
// g_z[r][o] = sum_c g_agg[r][c]*W[o][c] + bias[o]
// Block 64x128, BK=32, 8 warps (2M x 4N), warp tile 32x32 via m16n8k8.
// Smem (fragment order, floats):
//   A: [mt4][ks4][lane32][4]  (8KB/buf)
//   B: [nt16][ks4][lane32][2] (16KB/buf)
#define ABUF(b) ((b)*2048)
#define BBUF(b) (4096 + (b)*4096)
#define GEMM_SMEM (12288*4)     // 48KB

__device__ __forceinline__ uint32_t to_tf32(float x) {
    uint32_t y;
    asm("cvt.rna.tf32.f32 %0, %1;" : "=r"(y) : "f"(x));
    return y;
}
__device__ __forceinline__ void mma_tf32(float* c, const uint32_t* a, const uint32_t* b) {
    asm volatile(
        "mma.sync.aligned.m16n8k8.row.col.f32.tf32.tf32.f32 "
        "{%0,%1,%2,%3}, {%4,%5,%6,%7}, {%8,%9}, {%0,%1,%2,%3};"
        : "+f"(c[0]), "+f"(c[1]), "+f"(c[2]), "+f"(c[3])
        : "r"(a[0]), "r"(a[1]), "r"(a[2]), "r"(a[3]), "r"(b[0]), "r"(b[1]));
}

__device__ __forceinline__ void scatterA(float* sm, int buf, int idx, float4 av) {
    int row = idx >> 3, cg = idx & 7;
    int ks = cg >> 1, half = cg & 1;
    int mt = row >> 4, rin = row & 15, r8 = rin & 7, hi = rin >> 3;
    float* ab = &sm[ABUF(buf) + ((mt*4 + ks)*32)*4 + (hi + 2*half)];
    ab[(r8*4+0)*4] = __uint_as_float(to_tf32(av.x));
    ab[(r8*4+1)*4] = __uint_as_float(to_tf32(av.y));
    ab[(r8*4+2)*4] = __uint_as_float(to_tf32(av.z));
    ab[(r8*4+3)*4] = __uint_as_float(to_tf32(av.w));
}
__device__ __forceinline__ void scatterB(float* sm, int buf, int idx, float4 bv) {
    int row = idx >> 3, cg = idx & 7;
    int ks = cg >> 1, half = cg & 1;
    int nt = row >> 3, nin = row & 7;
    float* bb = &sm[BBUF(buf) + ((nt*4 + ks)*32)*2 + half];
    bb[(nin*4+0)*2] = __uint_as_float(to_tf32(bv.x));
    bb[(nin*4+1)*2] = __uint_as_float(to_tf32(bv.y));
    bb[(nin*4+2)*2] = __uint_as_float(to_tf32(bv.z));
    bb[(nin*4+3)*2] = __uint_as_float(to_tf32(bv.w));
}

__global__ void __launch_bounds__(256) k_gemm_mma(const float* __restrict__ W,
                                                  const float* __restrict__ bias) {
    extern __shared__ float sm[];
    int t = threadIdx.x;
    int lane = t & 31;
    int wid = t >> 5;
    int wm = wid >> 2, wn = wid & 3;          // warp: 32-row half, 32-col quarter
    int rBase = blockIdx.x * 64;
    int oBase = blockIdx.y * 128;
    const float* A = g_agg;

    float acc[2][4][4];
    #pragma unroll
    for (int mt = 0; mt < 2; mt++)
        #pragma unroll
        for (int nt = 0; nt < 4; nt++)
            #pragma unroll
            for (int j = 0; j < 4; j++) acc[mt][nt][j] = 0.0f;

    // ---- fill chunk 0 into buffer 0 ----
    {
        #pragma unroll
        for (int i = 0; i < 2; i++) {
            int idx = t + 256*i;   // 512 A float4s
            int row = idx >> 3, cg = idx & 7;
            scatterA(sm, 0, idx, *(const float4*)&A[(rBase+row)*DD + cg*4]);
        }
        #pragma unroll
        for (int i = 0; i < 4; i++) {
            int idx = t + 256*i;   // 1024 B float4s
            int row = idx >> 3, cg = idx & 7;
            scatterB(sm, 0, idx, *(const float4*)&W[(oBase+row)*DD + cg*4]);
        }
    }
    __syncthreads();

    #pragma unroll 1
    for (int it = 0; it < 16; it++) {
        int cur = it & 1;
        float4 sa[2], sb[4];
        if (it + 1 < 16) {   // stage next chunk's gmem loads in registers
            int k0 = (it + 1) * 32;
            #pragma unroll
            for (int i = 0; i < 2; i++) {
                int idx = t + 256*i;
                int row = idx >> 3, cg = idx & 7;
                sa[i] = *(const float4*)&A[(rBase+row)*DD + k0 + cg*4];
            }
            #pragma unroll
            for (int i = 0; i < 4; i++) {
                int idx = t + 256*i;
                int row = idx >> 3, cg = idx & 7;
                sb[i] = *(const float4*)&W[(oBase+row)*DD + k0 + cg*4];
            }
        }
        // ---- compute on current buffer (LDG latency hides here) ----
        #pragma unroll
        for (int ks = 0; ks < 4; ks++) {
            uint32_t af[2][4], bf[4][2];
            #pragma unroll
            for (int mt = 0; mt < 2; mt++) {
                const float4 v = *(const float4*)&sm[ABUF(cur) + (((wm*2+mt)*4 + ks)*32 + lane)*4];
                af[mt][0] = __float_as_uint(v.x); af[mt][1] = __float_as_uint(v.y);
                af[mt][2] = __float_as_uint(v.z); af[mt][3] = __float_as_uint(v.w);
            }
            #pragma unroll
            for (int nt = 0; nt < 4; nt++) {
                const float2 v = *(const float2*)&sm[BBUF(cur) + (((wn*4+nt)*4 + ks)*32 + lane)*2];
                bf[nt][0] = __float_as_uint(v.x); bf[nt][1] = __float_as_uint(v.y);
            }
            #pragma unroll
            for (int mt = 0; mt < 2; mt++)
                #pragma unroll
                for (int nt = 0; nt < 4; nt++)
                    mma_tf32(acc[mt][nt], af[mt], bf[nt]);
        }
        if (it + 1 < 16) {   // scatter staged regs into other buffer
            int nb = 1 - cur;
            #pragma unroll
            for (int i = 0; i < 2; i++) scatterA(sm, nb, t + 256*i, sa[i]);
            #pragma unroll
            for (int i = 0; i < 4; i++) scatterB(sm, nb, t + 256*i, sb[i]);
        }
        __syncthreads();
    }

    // ---- epilogue: bias add, write g_z ----
    #pragma unroll
    for (int nt = 0; nt < 4; nt++) {
        int col = oBase + wn*32 + nt*8 + (lane & 3)*2;
        float2 bv = *(const float2*)&bias[col];
        #pragma unroll
        for (int mt = 0; mt < 2; mt++) {
            int row0 = rBase + wm*32 + mt*16 + (lane >> 2);
            float2 v0 = make_float2(acc[mt][nt][0] + bv.x, acc[mt][nt][1] + bv.y);
            float2 v1 = make_float2(acc[mt][nt][2] + bv.x, acc[mt][nt][3] + bv.y);
            *(float2*)&g_z[row0*DD + col]     = v0;
            *(float2*)&g_z[(row0+8)*DD + col] = v1;
        }
    }
}

// ---------------- BN stats: deterministic 2-stage reduction ----------------
__global__ void k_stats() {
    int rb = blockIdx.x;
    int o  = threadIdx.x;
    float s = 0.0f, q = 0.0f;
    #pragma unroll 8
    for (int i = 0; i < 64; i++) {
        float v = g_z[(rb*64 + i)*DD + o];
        s += v; q += v*v;
    }
    g_psum[rb*DD + o] = s;
    g_psq [rb*DD + o] = q;
}

__global__ void k_finalize(const float* __restrict__ gma, const float* __restrict__ bta) {
    int o = threadIdx.x;
    float s = 0.0f, q = 0.0f;
    #pragma unroll 8
    for (int i = 0; i < 64; i++) { s += g_psum[i*DD + o]; q += g_psq[i*DD + o]; }
    float mean = s * (1.0f/4096.0f);
    float var  = q * (1.0f/4096.0f) - mean*mean;
    float inv  = rsqrtf(var + 1e-5f);
    float sc   = gma[o] * inv;
    g_scale[o] = sc;
    g_shift[o] = bta[o] - mean * sc;
}

// ---------------- BN apply + ReLU -> out[:, :, 15, :] ----------------
__global__ void k_apply(float* __restrict__ outp) {
    int i  = blockIdx.x * blockDim.x + threadIdx.x;  // float4 index
    int r  = i >> 7;
    int cw = i & 127;
    float4 z  = ((const float4*)g_z)[i];
    float4 sc = ((const float4*)g_scale)[cw];
    float4 sh = ((const float4*)g_shift)[cw];
    float4 h;
    h.x = fmaxf(fmaf(z.x, sc.x, sh.x), 0.0f);
    h.y = fmaxf(fmaf(z.y, sc.y, sh.y), 0.0f);
    h.z = fmaxf(fmaf(z.z, sc.z, sh.z), 0.0f);
    h.w = fmaxf(fmaf(z.w, sc.w, sh.w), 0.0f);
    *(float4*)&outp[r*(TT*DD) + 15*DD + cw*4] = h;
}

// ---------------- side stream + events (created pre-main, no allocs in launch) --
namespace {
struct SideStream {
    cudaStream_t s;
    cudaEvent_t evFork, evJoin;
    SideStream() {
        cudaStreamCreateWithFlags(&s, cudaStreamNonBlocking);
        cudaEventCreateWithFlags(&evFork, cudaEventDisableTiming);
        cudaEventCreateWithFlags(&evJoin, cudaEventDisableTiming);
        k_warm<<<1, 32, 0, s>>>();     // materialize stream resources now
        cudaStreamSynchronize(s);
    }
};
SideStream g_ss;
}

// ---------------- launcher ----------------
extern "C" void kernel_launch(void* const* d_in, const int* in_sizes, int n_in,
                              void* d_out, int out_size) {
    const float* pf  = (const float*)d_in[0];
    const float* bbx = (const float*)d_in[1];
    const float* w1  = (const float*)d_in[2];
    const float* b1  = (const float*)d_in[3];
    const float* g1  = (const float*)d_in[4];
    const float* be1 = (const float*)d_in[5];
    const float* w2  = (const float*)d_in[6];
    const float* b2  = (const float*)d_in[7];
    const float* g2  = (const float*)d_in[8];
    const float* be2 = (const float*)d_in[9];
    float* out = (float*)d_out;

    // fork: bulk copy of t=0..14 slices runs concurrently on the side stream
    cudaEventRecord(g_ss.evFork, 0);
    cudaStreamWaitEvent(g_ss.s, g_ss.evFork, 0);
    k_copy15<<<dim3(RR, 15), 128, 0, g_ss.s>>>((const float4*)pf, (float4*)out);
    cudaEventRecord(g_ss.evJoin, g_ss.s);

    // main compute chain (default stream)
    k_adj<<<64, 256>>>(bbx);

    // layer 1
    k_agg<<<dim3(64, 8), 256>>>(pf, 0);
    k_gemm_mma<<<dim3(64, 4), 256, GEMM_SMEM>>>(w1, b1);
    k_stats<<<64, 512>>>();
    k_finalize<<<1, 512>>>(g1, be1);

    // layer 2 (BN-apply of layer 1 fused into the aggregation load)
    k_agg<<<dim3(64, 8), 256>>>(nullptr, 1);
    k_gemm_mma<<<dim3(64, 4), 256, GEMM_SMEM>>>(w2, b2);
    k_stats<<<64, 512>>>();
    k_finalize<<<1, 512>>>(g2, be2);
    k_apply<<<2048, 256>>>(out);

    // join side stream before the graph/launch completes
    cudaStreamWaitEvent(0, g_ss.evJoin, 0);
}

// round 9
// speedup vs baseline: 1.5928x; 1.0296x over previous
#include <cuda_runtime.h>
#include <cstdint>

#define BB 64
#define NN 64
#define TT 16
#define DD 512
#define RR (BB*NN)          // 4096 rows (b,m)
#define THR2 (150.0f*150.0f)

// ---------------- scratch (device globals, no allocation) ----------------
__device__ float g_agg[RR*DD];      // aggregation output  [r][c]
__device__ float g_z[RR*DD];        // pre-BN GEMM output  [r][o]
__device__ float g_psum[64*DD];     // BN partial sums   [rTile][col]
__device__ float g_psq[64*DD];      // BN partial sumsq  [rTile][col]
__device__ float g_scale[DD];
__device__ float g_shift[DD];

// ---------------- warmup (forces stream resource materialization pre-main) --
__global__ void k_warm() {}

// ---------------- side-stream copy: out[:, :, t!=15, :] = pf ----------------
// grid (64, 15), 256 threads; each block copies 64 rows x 128 float4 of slice t
__global__ void __launch_bounds__(256) k_copy15(const float4* __restrict__ src,
                                                float4* __restrict__ dst) {
    int t  = threadIdx.x;
    int tt = blockIdx.y;          // 0..14
    int rb = blockIdx.x;          // 0..63
    #pragma unroll 4
    for (int j = t; j < 64*128; j += 256) {
        int k = j >> 7, w = j & 127;
        size_t idx = ((size_t)(rb*64 + k)*16 + tt) * 128 + w;
        dst[idx] = src[idx];
    }
}

// ---------------- graph aggregation (adjacency fused) ----------------
// Asm[m][n] = A_norm^T = A[n][m]/deg[n]; computed in-smem from bboxes.
// mode 0: x[n][c] = pf[b][n][15][c]
// mode 1: x[n][c] = relu(g_z[b*NN+n][c]*scale[c] + shift[c])  (fused layer-1 BN apply)
__global__ void __launch_bounds__(256) k_agg(const float* __restrict__ pf,
                                             const float* __restrict__ bbx, int mode) {
    __shared__ float Asm[NN*NN];
    __shared__ float Xs[NN][68];
    __shared__ float cx[NN], cy[NN], invdeg[NN];
    int b = blockIdx.x;
    int cBase = blockIdx.y * 64;
    int t = threadIdx.x;

    if (t < NN) {
        const float* p = bbx + (b*NN + t)*4;
        cx[t] = p[0] + 0.5f*p[2];
        cy[t] = p[1] + 0.5f*p[3];
    }
    __syncthreads();
    if (t < NN) {
        float x0 = cx[t], y0 = cy[t];
        int cnt = 0;
        #pragma unroll 8
        for (int m = 0; m < NN; m++) {
            float dx = x0 - cx[m], dy = y0 - cy[m];
            if (m != t && dx*dx + dy*dy < THR2) cnt++;
        }
        invdeg[t] = 1.0f / ((float)(cnt + 1) + 1e-6f);
    }
    __syncthreads();
    #pragma unroll
    for (int i = 0; i < 16; i++) {
        int e = t + 256*i;
        int m = e >> 6, n = e & 63;
        float dx = cx[n]-cx[m], dy = cy[n]-cy[m];
        float d2 = dx*dx + dy*dy;
        Asm[e] = (n == m || d2 < THR2) ? invdeg[n] : 0.0f;
    }
    #pragma unroll
    for (int i = 0; i < 4; i++) {
        int e  = t + 256*i;
        int n  = e >> 4;
        int cg = (e & 15) * 4;
        float4 v;
        if (mode == 0) {
            v = *(const float4*)&pf[((b*NN + n)*TT + 15)*DD + cBase + cg];
        } else {
            float4 z  = *(const float4*)&g_z[(b*NN + n)*DD + cBase + cg];
            float4 sc = *(const float4*)&g_scale[cBase + cg];
            float4 sh = *(const float4*)&g_shift[cBase + cg];
            v.x = fmaxf(fmaf(z.x, sc.x, sh.x), 0.0f);
            v.y = fmaxf(fmaf(z.y, sc.y, sh.y), 0.0f);
            v.z = fmaxf(fmaf(z.z, sc.z, sh.z), 0.0f);
            v.w = fmaxf(fmaf(z.w, sc.w, sh.w), 0.0f);
        }
        *(float4*)&Xs[n][cg] = v;
    }
    __syncthreads();

    int ty = t >> 4, tx = t & 15;
    int m0 = ty * 4, c0 = tx * 4;
    float acc[4][4] = {};
    for (int n = 0; n < NN; n++) {
        float a0 = Asm[(m0+0)*NN + n];
        float a1 = Asm[(m0+1)*NN + n];
        float a2 = Asm[(m0+2)*NN + n];
        float a3 = Asm[(m0+3)*NN + n];
        float4 xv = *(const float4*)&Xs[n][c0];
        acc[0][0] += a0*xv.x; acc[0][1] += a0*xv.y; acc[0][2] += a0*xv.z; acc[0][3] += a0*xv.w;
        acc[1][0] += a1*xv.x; acc[1][1] += a1*xv.y; acc[1][2] += a1*xv.z; acc[1][3] += a1*xv.w;
        acc[2][0] += a2*xv.x; acc[2][1] += a2*xv.y; acc[2][2] += a2*xv.z; acc[2][3] += a2*xv.w;
        acc[3][0] += a3*xv.x; acc[3][1] += a3*xv.y; acc[3][2] += a3*xv.z; acc[3][3] += a3*xv.w;
    }
    #pragma unroll
    for (int i = 0; i < 4; i++) {
        float4 v = make_float4(acc[i][0], acc[i][1], acc[i][2], acc[i][3]);
        *(float4*)&g_agg[(b*NN + m0 + i)*DD + cBase + c0] = v;
    }
}

// ---------------- tf32 mma.sync GEMM + fused BN partial stats ----------------
// g_z[r][o] = sum_c g_agg[r][c]*W[o][c] + bias[o]
// Block 64x128, BK=32, 8 warps (2M x 4N), warp tile 32x32 via m16n8k8.
#define ABUF(b) ((b)*2048)
#define BBUF(b) (4096 + (b)*4096)
#define GEMM_SMEM (12288*4)     // 48KB

__device__ __forceinline__ uint32_t to_tf32(float x) {
    uint32_t y;
    asm("cvt.rna.tf32.f32 %0, %1;" : "=r"(y) : "f"(x));
    return y;
}
__device__ __forceinline__ void mma_tf32(float* c, const uint32_t* a, const uint32_t* b) {
    asm volatile(
        "mma.sync.aligned.m16n8k8.row.col.f32.tf32.tf32.f32 "
        "{%0,%1,%2,%3}, {%4,%5,%6,%7}, {%8,%9}, {%0,%1,%2,%3};"
        : "+f"(c[0]), "+f"(c[1]), "+f"(c[2]), "+f"(c[3])
        : "r"(a[0]), "r"(a[1]), "r"(a[2]), "r"(a[3]), "r"(b[0]), "r"(b[1]));
}

__device__ __forceinline__ void scatterA(float* sm, int buf, int idx, float4 av) {
    int row = idx >> 3, cg = idx & 7;
    int ks = cg >> 1, half = cg & 1;
    int mt = row >> 4, rin = row & 15, r8 = rin & 7, hi = rin >> 3;
    float* ab = &sm[ABUF(buf) + ((mt*4 + ks)*32)*4 + (hi + 2*half)];
    ab[(r8*4+0)*4] = __uint_as_float(to_tf32(av.x));
    ab[(r8*4+1)*4] = __uint_as_float(to_tf32(av.y));
    ab[(r8*4+2)*4] = __uint_as_float(to_tf32(av.z));
    ab[(r8*4+3)*4] = __uint_as_float(to_tf32(av.w));
}
__device__ __forceinline__ void scatterB(float* sm, int buf, int idx, float4 bv) {
    int row = idx >> 3, cg = idx & 7;
    int ks = cg >> 1, half = cg & 1;
    int nt = row >> 3, nin = row & 7;
    float* bb = &sm[BBUF(buf) + ((nt*4 + ks)*32)*2 + half];
    bb[(nin*4+0)*2] = __uint_as_float(to_tf32(bv.x));
    bb[(nin*4+1)*2] = __uint_as_float(to_tf32(bv.y));
    bb[(nin*4+2)*2] = __uint_as_float(to_tf32(bv.z));
    bb[(nin*4+3)*2] = __uint_as_float(to_tf32(bv.w));
}

__global__ void __launch_bounds__(256) k_gemm_mma(const float* __restrict__ W,
                                                  const float* __restrict__ bias) {
    extern __shared__ float sm[];
    int t = threadIdx.x;
    int lane = t & 31;
    int wid = t >> 5;
    int wm = wid >> 2, wn = wid & 3;          // warp: 32-row half, 32-col quarter
    int rBase = blockIdx.x * 64;
    int oBase = blockIdx.y * 128;
    const float* A = g_agg;

    float acc[2][4][4];
    #pragma unroll
    for (int mt = 0; mt < 2; mt++)
        #pragma unroll
        for (int nt = 0; nt < 4; nt++)
            #pragma unroll
            for (int j = 0; j < 4; j++) acc[mt][nt][j] = 0.0f;

    // ---- fill chunk 0 into buffer 0 ----
    {
        #pragma unroll
        for (int i = 0; i < 2; i++) {
            int idx = t + 256*i;
            int row = idx >> 3, cg = idx & 7;
            scatterA(sm, 0, idx, *(const float4*)&A[(rBase+row)*DD + cg*4]);
        }
        #pragma unroll
        for (int i = 0; i < 4; i++) {
            int idx = t + 256*i;
            int row = idx >> 3, cg = idx & 7;
            scatterB(sm, 0, idx, *(const float4*)&W[(oBase+row)*DD + cg*4]);
        }
    }
    __syncthreads();

    #pragma unroll 1
    for (int it = 0; it < 16; it++) {
        int cur = it & 1;
        float4 sa[2], sb[4];
        if (it + 1 < 16) {   // stage next chunk's gmem loads in registers
            int k0 = (it + 1) * 32;
            #pragma unroll
            for (int i = 0; i < 2; i++) {
                int idx = t + 256*i;
                int row = idx >> 3, cg = idx & 7;
                sa[i] = *(const float4*)&A[(rBase+row)*DD + k0 + cg*4];
            }
            #pragma unroll
            for (int i = 0; i < 4; i++) {
                int idx = t + 256*i;
                int row = idx >> 3, cg = idx & 7;
                sb[i] = *(const float4*)&W[(oBase+row)*DD + k0 + cg*4];
            }
        }
        // ---- compute on current buffer (LDG latency hides here) ----
        #pragma unroll
        for (int ks = 0; ks < 4; ks++) {
            uint32_t af[2][4], bf[4][2];
            #pragma unroll
            for (int mt = 0; mt < 2; mt++) {
                const float4 v = *(const float4*)&sm[ABUF(cur) + (((wm*2+mt)*4 + ks)*32 + lane)*4];
                af[mt][0] = __float_as_uint(v.x); af[mt][1] = __float_as_uint(v.y);
                af[mt][2] = __float_as_uint(v.z); af[mt][3] = __float_as_uint(v.w);
            }
            #pragma unroll
            for (int nt = 0; nt < 4; nt++) {
                const float2 v = *(const float2*)&sm[BBUF(cur) + (((wn*4+nt)*4 + ks)*32 + lane)*2];
                bf[nt][0] = __float_as_uint(v.x); bf[nt][1] = __float_as_uint(v.y);
            }
            #pragma unroll
            for (int mt = 0; mt < 2; mt++)
                #pragma unroll
                for (int nt = 0; nt < 4; nt++)
                    mma_tf32(acc[mt][nt], af[mt], bf[nt]);
        }
        if (it + 1 < 16) {
            int nb = 1 - cur;
            #pragma unroll
            for (int i = 0; i < 2; i++) scatterA(sm, nb, t + 256*i, sa[i]);
            #pragma unroll
            for (int i = 0; i < 4; i++) scatterB(sm, nb, t + 256*i, sb[i]);
        }
        __syncthreads();
    }

    // ---- epilogue: bias add, write g_z, accumulate per-column stats ----
    float s[4][2], q[4][2];
    #pragma unroll
    for (int nt = 0; nt < 4; nt++) { s[nt][0]=s[nt][1]=q[nt][0]=q[nt][1]=0.0f; }

    #pragma unroll
    for (int nt = 0; nt < 4; nt++) {
        int col = oBase + wn*32 + nt*8 + (lane & 3)*2;
        float2 bv = *(const float2*)&bias[col];
        #pragma unroll
        for (int mt = 0; mt < 2; mt++) {
            int row0 = rBase + wm*32 + mt*16 + (lane >> 2);
            float2 v0 = make_float2(acc[mt][nt][0] + bv.x, acc[mt][nt][1] + bv.y);
            float2 v1 = make_float2(acc[mt][nt][2] + bv.x, acc[mt][nt][3] + bv.y);
            *(float2*)&g_z[row0*DD + col]     = v0;
            *(float2*)&g_z[(row0+8)*DD + col] = v1;
            s[nt][0] += v0.x + v1.x;  s[nt][1] += v0.y + v1.y;
            q[nt][0] += v0.x*v0.x + v1.x*v1.x;
            q[nt][1] += v0.y*v0.y + v1.y*v1.y;
        }
    }
    // reduce across lanes with same (lane&3): xor 4, 8, 16
    #pragma unroll
    for (int off = 4; off < 32; off <<= 1) {
        #pragma unroll
        for (int nt = 0; nt < 4; nt++) {
            s[nt][0] += __shfl_xor_sync(0xffffffffu, s[nt][0], off);
            s[nt][1] += __shfl_xor_sync(0xffffffffu, s[nt][1], off);
            q[nt][0] += __shfl_xor_sync(0xffffffffu, q[nt][0], off);
            q[nt][1] += __shfl_xor_sync(0xffffffffu, q[nt][1], off);
        }
    }
    // smem combine across the two wm warps: red[wm][{s,q}][128 cols]
    float* red = sm;                      // reuse (all warps past final sync)
    __syncthreads();
    if (lane < 4) {
        #pragma unroll
        for (int nt = 0; nt < 4; nt++) {
            int coll = wn*32 + nt*8 + lane*2;
            red[wm*256 +       coll    ] = s[nt][0];
            red[wm*256 +       coll + 1] = s[nt][1];
            red[wm*256 + 128 + coll    ] = q[nt][0];
            red[wm*256 + 128 + coll + 1] = q[nt][1];
        }
    }
    __syncthreads();
    if (t < 128) {
        float st = red[t]       + red[256 + t];
        float qt = red[128 + t] + red[384 + t];
        g_psum[blockIdx.x*DD + oBase + t] = st;
        g_psq [blockIdx.x*DD + oBase + t] = qt;
    }
}

// ---------------- BN finalize ----------------
__global__ void k_finalize(const float* __restrict__ gma, const float* __restrict__ bta) {
    int o = threadIdx.x;
    float s = 0.0f, q = 0.0f;
    #pragma unroll 8
    for (int i = 0; i < 64; i++) { s += g_psum[i*DD + o]; q += g_psq[i*DD + o]; }
    float mean = s * (1.0f/4096.0f);
    float var  = q * (1.0f/4096.0f) - mean*mean;
    float inv  = rsqrtf(var + 1e-5f);
    float sc   = gma[o] * inv;
    g_scale[o] = sc;
    g_shift[o] = bta[o] - mean * sc;
}

// ---------------- BN apply + ReLU -> out[:, :, 15, :] ----------------
__global__ void k_apply(float* __restrict__ outp) {
    int i  = blockIdx.x * blockDim.x + threadIdx.x;  // float4 index
    int r  = i >> 7;
    int cw = i & 127;
    float4 z  = ((const float4*)g_z)[i];
    float4 sc = ((const float4*)g_scale)[cw];
    float4 sh = ((const float4*)g_shift)[cw];
    float4 h;
    h.x = fmaxf(fmaf(z.x, sc.x, sh.x), 0.0f);
    h.y = fmaxf(fmaf(z.y, sc.y, sh.y), 0.0f);
    h.z = fmaxf(fmaf(z.z, sc.z, sh.z), 0.0f);
    h.w = fmaxf(fmaf(z.w, sc.w, sh.w), 0.0f);
    *(float4*)&outp[r*(TT*DD) + 15*DD + cw*4] = h;
}

// ---------------- side stream + events (created pre-main, no allocs in launch) --
namespace {
struct SideStream {
    cudaStream_t s;
    cudaEvent_t evFork, evJoin;
    SideStream() {
        cudaStreamCreateWithFlags(&s, cudaStreamNonBlocking);
        cudaEventCreateWithFlags(&evFork, cudaEventDisableTiming);
        cudaEventCreateWithFlags(&evJoin, cudaEventDisableTiming);
        k_warm<<<1, 32, 0, s>>>();     // materialize stream resources now
        cudaStreamSynchronize(s);
    }
};
SideStream g_ss;
}

// ---------------- launcher ----------------
extern "C" void kernel_launch(void* const* d_in, const int* in_sizes, int n_in,
                              void* d_out, int out_size) {
    const float* pf  = (const float*)d_in[0];
    const float* bbx = (const float*)d_in[1];
    const float* w1  = (const float*)d_in[2];
    const float* b1  = (const float*)d_in[3];
    const float* g1  = (const float*)d_in[4];
    const float* be1 = (const float*)d_in[5];
    const float* w2  = (const float*)d_in[6];
    const float* b2  = (const float*)d_in[7];
    const float* g2  = (const float*)d_in[8];
    const float* be2 = (const float*)d_in[9];
    float* out = (float*)d_out;

    static int s_attr_done = 0;
    if (!s_attr_done) {
        cudaFuncSetAttribute(k_gemm_mma, cudaFuncAttributeMaxDynamicSharedMemorySize, GEMM_SMEM);
        s_attr_done = 1;
    }

    // fork: bulk copy of t=0..14 slices runs concurrently on the side stream
    cudaEventRecord(g_ss.evFork, 0);
    cudaStreamWaitEvent(g_ss.s, g_ss.evFork, 0);
    k_copy15<<<dim3(64, 15), 256, 0, g_ss.s>>>((const float4*)pf, (float4*)out);
    cudaEventRecord(g_ss.evJoin, g_ss.s);

    // layer 1
    k_agg<<<dim3(64, 8), 256>>>(pf, bbx, 0);
    k_gemm_mma<<<dim3(64, 4), 256, GEMM_SMEM>>>(w1, b1);
    k_finalize<<<1, 512>>>(g1, be1);

    // layer 2 (BN-apply of layer 1 fused into the aggregation load)
    k_agg<<<dim3(64, 8), 256>>>(nullptr, bbx, 1);
    k_gemm_mma<<<dim3(64, 4), 256, GEMM_SMEM>>>(w2, b2);
    k_finalize<<<1, 512>>>(g2, be2);
    k_apply<<<2048, 256>>>(out);

    // join side stream before the graph/launch completes
    cudaStreamWaitEvent(0, g_ss.evJoin, 0);
}

// round 10
// speedup vs baseline: 1.8708x; 1.1746x over previous
#include <cuda_runtime.h>
#include <cstdint>

#define BB 64
#define NN 64
#define TT 16
#define DD 512
#define RR (BB*NN)          // 4096 rows (b,m)
#define THR2 (150.0f*150.0f)

// ---------------- scratch (device globals, no allocation) ----------------
__device__ float g_agg[RR*DD];      // aggregation output  [r][c]
__device__ float g_z[RR*DD];        // pre-BN GEMM output  [r][o]
__device__ float g_psum[64*DD];     // BN partial sums   [rTile][col]
__device__ float g_psq[64*DD];      // BN partial sumsq  [rTile][col]
__device__ float g_scale[DD];
__device__ float g_shift[DD];

// ---------------- warmup (forces stream resource materialization pre-main) --
__global__ void k_warm() {}

// ---------------- side-stream copy: out[:, :, t!=15, :] = pf ----------------
__global__ void __launch_bounds__(256) k_copy15(const float4* __restrict__ src,
                                                float4* __restrict__ dst) {
    int t  = threadIdx.x;
    int tt = blockIdx.y;          // 0..14
    int rb = blockIdx.x;          // 0..63
    #pragma unroll 4
    for (int j = t; j < 64*128; j += 256) {
        int k = j >> 7, w = j & 127;
        size_t idx = ((size_t)(rb*64 + k)*16 + tt) * 128 + w;
        dst[idx] = src[idx];
    }
}

// ---------------- graph aggregation (adjacency fused) ----------------
__global__ void __launch_bounds__(256) k_agg(const float* __restrict__ pf,
                                             const float* __restrict__ bbx, int mode) {
    __shared__ float Asm[NN*NN];
    __shared__ float Xs[NN][68];
    __shared__ float cx[NN], cy[NN], invdeg[NN];
    int b = blockIdx.x;
    int cBase = blockIdx.y * 64;
    int t = threadIdx.x;

    if (t < NN) {
        const float* p = bbx + (b*NN + t)*4;
        cx[t] = p[0] + 0.5f*p[2];
        cy[t] = p[1] + 0.5f*p[3];
    }
    __syncthreads();
    if (t < NN) {
        float x0 = cx[t], y0 = cy[t];
        int cnt = 0;
        #pragma unroll 8
        for (int m = 0; m < NN; m++) {
            float dx = x0 - cx[m], dy = y0 - cy[m];
            if (m != t && dx*dx + dy*dy < THR2) cnt++;
        }
        invdeg[t] = 1.0f / ((float)(cnt + 1) + 1e-6f);
    }
    __syncthreads();
    #pragma unroll
    for (int i = 0; i < 16; i++) {
        int e = t + 256*i;
        int m = e >> 6, n = e & 63;
        float dx = cx[n]-cx[m], dy = cy[n]-cy[m];
        float d2 = dx*dx + dy*dy;
        Asm[e] = (n == m || d2 < THR2) ? invdeg[n] : 0.0f;
    }
    #pragma unroll
    for (int i = 0; i < 4; i++) {
        int e  = t + 256*i;
        int n  = e >> 4;
        int cg = (e & 15) * 4;
        float4 v;
        if (mode == 0) {
            v = *(const float4*)&pf[((b*NN + n)*TT + 15)*DD + cBase + cg];
        } else {
            float4 z  = *(const float4*)&g_z[(b*NN + n)*DD + cBase + cg];
            float4 sc = *(const float4*)&g_scale[cBase + cg];
            float4 sh = *(const float4*)&g_shift[cBase + cg];
            v.x = fmaxf(fmaf(z.x, sc.x, sh.x), 0.0f);
            v.y = fmaxf(fmaf(z.y, sc.y, sh.y), 0.0f);
            v.z = fmaxf(fmaf(z.z, sc.z, sh.z), 0.0f);
            v.w = fmaxf(fmaf(z.w, sc.w, sh.w), 0.0f);
        }
        *(float4*)&Xs[n][cg] = v;
    }
    __syncthreads();

    int ty = t >> 4, tx = t & 15;
    int m0 = ty * 4, c0 = tx * 4;
    float acc[4][4] = {};
    for (int n = 0; n < NN; n++) {
        float a0 = Asm[(m0+0)*NN + n];
        float a1 = Asm[(m0+1)*NN + n];
        float a2 = Asm[(m0+2)*NN + n];
        float a3 = Asm[(m0+3)*NN + n];
        float4 xv = *(const float4*)&Xs[n][c0];
        acc[0][0] += a0*xv.x; acc[0][1] += a0*xv.y; acc[0][2] += a0*xv.z; acc[0][3] += a0*xv.w;
        acc[1][0] += a1*xv.x; acc[1][1] += a1*xv.y; acc[1][2] += a1*xv.z; acc[1][3] += a1*xv.w;
        acc[2][0] += a2*xv.x; acc[2][1] += a2*xv.y; acc[2][2] += a2*xv.z; acc[2][3] += a2*xv.w;
        acc[3][0] += a3*xv.x; acc[3][1] += a3*xv.y; acc[3][2] += a3*xv.z; acc[3][3] += a3*xv.w;
    }
    #pragma unroll
    for (int i = 0; i < 4; i++) {
        float4 v = make_float4(acc[i][0], acc[i][1], acc[i][2], acc[i][3]);
        *(float4*)&g_agg[(b*NN + m0 + i)*DD + cBase + c0] = v;
    }
}

// ---------------- tf32 mma.sync GEMM + fused BN partial stats ----------------
// g_z[r][o] = sum_c g_agg[r][c]*W[o][c] + bias[o]
// Block 64x128, BK=32, 8 warps (2M x 4N), warp tile 32x32 via m16n8k8.
// Smem: plain K-major, stride 36 floats (32 data + 4 pad):
//   A: [64][36]  per buf (2304 floats)   B: [128][36] per buf (4608 floats)
#define LDK 36
#define ABUF(b) ((b)*2304)
#define BBUF(b) (4608 + (b)*4608)
#define GEMM_SMEM (13824*4)     // 54KB

__device__ __forceinline__ void mma_tf32(float* c, const uint32_t* a, const uint32_t* b) {
    asm volatile(
        "mma.sync.aligned.m16n8k8.row.col.f32.tf32.tf32.f32 "
        "{%0,%1,%2,%3}, {%4,%5,%6,%7}, {%8,%9}, {%0,%1,%2,%3};"
        : "+f"(c[0]), "+f"(c[1]), "+f"(c[2]), "+f"(c[3])
        : "r"(a[0]), "r"(a[1]), "r"(a[2]), "r"(a[3]), "r"(b[0]), "r"(b[1]));
}

__global__ void __launch_bounds__(256) k_gemm_mma(const float* __restrict__ W,
                                                  const float* __restrict__ bias) {
    extern __shared__ float sm[];
    int t = threadIdx.x;
    int lane = t & 31;
    int wid = t >> 5;
    int wm = wid >> 2, wn = wid & 3;          // warp: 32-row half, 32-col quarter
    int rBase = blockIdx.x * 64;
    int oBase = blockIdx.y * 128;
    const float* A = g_agg;

    // fill indexing: each thread owns (row = t>>3, cg = t&7) (+256 stride)
    int frow = t >> 3, fcg = (t & 7) * 4;

    // fragment base offsets (floats) within a buffer
    int aBase = (wm*32 + (lane >> 2))*LDK + (lane & 3);   // + mt*16*LDK + 8*LDK*(j&1) + ks*8 + 4*(j>>1)
    int bBase = (wn*32 + (lane >> 2))*LDK + (lane & 3);   // + nt*8*LDK + ks*8 + 4*j

    float acc[2][4][4];
    #pragma unroll
    for (int mt = 0; mt < 2; mt++)
        #pragma unroll
        for (int nt = 0; nt < 4; nt++)
            #pragma unroll
            for (int j = 0; j < 4; j++) acc[mt][nt][j] = 0.0f;

    // ---- fill chunk 0 into buffer 0 ----
    {
        #pragma unroll
        for (int i = 0; i < 2; i++) {
            int row = frow + 32*i;
            *(float4*)&sm[ABUF(0) + row*LDK + fcg] = *(const float4*)&A[(rBase+row)*DD + fcg];
        }
        #pragma unroll
        for (int i = 0; i < 4; i++) {
            int row = frow + 32*i;
            *(float4*)&sm[BBUF(0) + row*LDK + fcg] = *(const float4*)&W[(oBase+row)*DD + fcg];
        }
    }
    __syncthreads();

    #pragma unroll 1
    for (int it = 0; it < 16; it++) {
        int cur = it & 1;
        float4 sa[2], sb[4];
        if (it + 1 < 16) {   // stage next chunk's gmem loads in registers
            int k0 = (it + 1) * 32;
            #pragma unroll
            for (int i = 0; i < 2; i++) {
                int row = frow + 32*i;
                sa[i] = *(const float4*)&A[(rBase+row)*DD + k0 + fcg];
            }
            #pragma unroll
            for (int i = 0; i < 4; i++) {
                int row = frow + 32*i;
                sb[i] = *(const float4*)&W[(oBase+row)*DD + k0 + fcg];
            }
        }
        // ---- compute on current buffer (LDG latency hides here) ----
        const float* as = &sm[ABUF(cur) + aBase];
        const float* bs = &sm[BBUF(cur) + bBase];
        #pragma unroll
        for (int ks = 0; ks < 4; ks++) {
            uint32_t af[2][4], bf[4][2];
            #pragma unroll
            for (int mt = 0; mt < 2; mt++) {
                #pragma unroll
                for (int j = 0; j < 4; j++)
                    af[mt][j] = __float_as_uint(as[(mt*16 + 8*(j&1))*LDK + ks*8 + 4*(j>>1)]);
            }
            #pragma unroll
            for (int nt = 0; nt < 4; nt++) {
                #pragma unroll
                for (int j = 0; j < 2; j++)
                    bf[nt][j] = __float_as_uint(bs[(nt*8)*LDK + ks*8 + 4*j]);
            }
            #pragma unroll
            for (int mt = 0; mt < 2; mt++)
                #pragma unroll
                for (int nt = 0; nt < 4; nt++)
                    mma_tf32(acc[mt][nt], af[mt], bf[nt]);
        }
        if (it + 1 < 16) {
            int nb = 1 - cur;
            #pragma unroll
            for (int i = 0; i < 2; i++)
                *(float4*)&sm[ABUF(nb) + (frow + 32*i)*LDK + fcg] = sa[i];
            #pragma unroll
            for (int i = 0; i < 4; i++)
                *(float4*)&sm[BBUF(nb) + (frow + 32*i)*LDK + fcg] = sb[i];
        }
        __syncthreads();
    }

    // ---- epilogue: bias add, write g_z, accumulate per-column stats ----
    float s[4][2], q[4][2];
    #pragma unroll
    for (int nt = 0; nt < 4; nt++) { s[nt][0]=s[nt][1]=q[nt][0]=q[nt][1]=0.0f; }

    #pragma unroll
    for (int nt = 0; nt < 4; nt++) {
        int col = oBase + wn*32 + nt*8 + (lane & 3)*2;
        float2 bv = *(const float2*)&bias[col];
        #pragma unroll
        for (int mt = 0; mt < 2; mt++) {
            int row0 = rBase + wm*32 + mt*16 + (lane >> 2);
            float2 v0 = make_float2(acc[mt][nt][0] + bv.x, acc[mt][nt][1] + bv.y);
            float2 v1 = make_float2(acc[mt][nt][2] + bv.x, acc[mt][nt][3] + bv.y);
            *(float2*)&g_z[row0*DD + col]     = v0;
            *(float2*)&g_z[(row0+8)*DD + col] = v1;
            s[nt][0] += v0.x + v1.x;  s[nt][1] += v0.y + v1.y;
            q[nt][0] += v0.x*v0.x + v1.x*v1.x;
            q[nt][1] += v0.y*v0.y + v1.y*v1.y;
        }
    }
    #pragma unroll
    for (int off = 4; off < 32; off <<= 1) {
        #pragma unroll
        for (int nt = 0; nt < 4; nt++) {
            s[nt][0] += __shfl_xor_sync(0xffffffffu, s[nt][0], off);
            s[nt][1] += __shfl_xor_sync(0xffffffffu, s[nt][1], off);
            q[nt][0] += __shfl_xor_sync(0xffffffffu, q[nt][0], off);
            q[nt][1] += __shfl_xor_sync(0xffffffffu, q[nt][1], off);
        }
    }
    float* red = sm;
    __syncthreads();
    if (lane < 4) {
        #pragma unroll
        for (int nt = 0; nt < 4; nt++) {
            int coll = wn*32 + nt*8 + lane*2;
            red[wm*256 +       coll    ] = s[nt][0];
            red[wm*256 +       coll + 1] = s[nt][1];
            red[wm*256 + 128 + coll    ] = q[nt][0];
            red[wm*256 + 128 + coll + 1] = q[nt][1];
        }
    }
    __syncthreads();
    if (t < 128) {
        float st = red[t]       + red[256 + t];
        float qt = red[128 + t] + red[384 + t];
        g_psum[blockIdx.x*DD + oBase + t] = st;
        g_psq [blockIdx.x*DD + oBase + t] = qt;
    }
}

// ---------------- BN finalize ----------------
__global__ void k_finalize(const float* __restrict__ gma, const float* __restrict__ bta) {
    int o = threadIdx.x;
    float s = 0.0f, q = 0.0f;
    #pragma unroll 8
    for (int i = 0; i < 64; i++) { s += g_psum[i*DD + o]; q += g_psq[i*DD + o]; }
    float mean = s * (1.0f/4096.0f);
    float var  = q * (1.0f/4096.0f) - mean*mean;
    float inv  = rsqrtf(var + 1e-5f);
    float sc   = gma[o] * inv;
    g_scale[o] = sc;
    g_shift[o] = bta[o] - mean * sc;
}

// ---------------- BN apply + ReLU -> out[:, :, 15, :] ----------------
__global__ void k_apply(float* __restrict__ outp) {
    int i  = blockIdx.x * blockDim.x + threadIdx.x;
    int r  = i >> 7;
    int cw = i & 127;
    float4 z  = ((const float4*)g_z)[i];
    float4 sc = ((const float4*)g_scale)[cw];
    float4 sh = ((const float4*)g_shift)[cw];
    float4 h;
    h.x = fmaxf(fmaf(z.x, sc.x, sh.x), 0.0f);
    h.y = fmaxf(fmaf(z.y, sc.y, sh.y), 0.0f);
    h.z = fmaxf(fmaf(z.z, sc.z, sh.z), 0.0f);
    h.w = fmaxf(fmaf(z.w, sc.w, sh.w), 0.0f);
    *(float4*)&outp[r*(TT*DD) + 15*DD + cw*4] = h;
}

// ---------------- side stream + events (created pre-main, no allocs in launch) --
namespace {
struct SideStream {
    cudaStream_t s;
    cudaEvent_t evFork, evJoin;
    SideStream() {
        cudaStreamCreateWithFlags(&s, cudaStreamNonBlocking);
        cudaEventCreateWithFlags(&evFork, cudaEventDisableTiming);
        cudaEventCreateWithFlags(&evJoin, cudaEventDisableTiming);
        k_warm<<<1, 32, 0, s>>>();
        cudaStreamSynchronize(s);
    }
};
SideStream g_ss;
}

// ---------------- launcher ----------------
extern "C" void kernel_launch(void* const* d_in, const int* in_sizes, int n_in,
                              void* d_out, int out_size) {
    const float* pf  = (const float*)d_in[0];
    const float* bbx = (const float*)d_in[1];
    const float* w1  = (const float*)d_in[2];
    const float* b1  = (const float*)d_in[3];
    const float* g1  = (const float*)d_in[4];
    const float* be1 = (const float*)d_in[5];
    const float* w2  = (const float*)d_in[6];
    const float* b2  = (const float*)d_in[7];
    const float* g2  = (const float*)d_in[8];
    const float* be2 = (const float*)d_in[9];
    float* out = (float*)d_out;

    static int s_attr_done = 0;
    if (!s_attr_done) {
        cudaFuncSetAttribute(k_gemm_mma, cudaFuncAttributeMaxDynamicSharedMemorySize, GEMM_SMEM);
        s_attr_done = 1;
    }

    // fork: bulk copy of t=0..14 slices runs concurrently on the side stream
    cudaEventRecord(g_ss.evFork, 0);
    cudaStreamWaitEvent(g_ss.s, g_ss.evFork, 0);
    k_copy15<<<dim3(64, 15), 256, 0, g_ss.s>>>((const float4*)pf, (float4*)out);
    cudaEventRecord(g_ss.evJoin, g_ss.s);

    // layer 1
    k_agg<<<dim3(64, 8), 256>>>(pf, bbx, 0);
    k_gemm_mma<<<dim3(64, 4), 256, GEMM_SMEM>>>(w1, b1);
    k_finalize<<<1, 512>>>(g1, be1);

    // layer 2 (BN-apply of layer 1 fused into the aggregation load)
    k_agg<<<dim3(64, 8), 256>>>(nullptr, bbx, 1);
    k_gemm_mma<<<dim3(64, 4), 256, GEMM_SMEM>>>(w2, b2);
    k_finalize<<<1, 512>>>(g2, be2);
    k_apply<<<2048, 256>>>(out);

    // join side stream before the graph/launch completes
    cudaStreamWaitEvent(0, g_ss.evJoin, 0);
}

// round 11
// speedup vs baseline: 1.9331x; 1.0333x over previous
#include <cuda_runtime.h>
#include <cstdint>

#define BB 64
#define NN 64
#define TT 16
#define DD 512
#define RR (BB*NN)          // 4096 rows (b,m)
#define THR2 (150.0f*150.0f)

// ---------------- scratch (device globals, no allocation) ----------------
__device__ float g_agg[RR*DD];      // aggregation output  [r][c]
__device__ float g_z[RR*DD];        // pre-BN GEMM output  [r][o]
__device__ float g_psum[64*DD];     // BN partial sums   [rTile][col]
__device__ float g_psq[64*DD];      // BN partial sumsq  [rTile][col]
__device__ float g_scale[DD];
__device__ float g_shift[DD];

// ---------------- warmup (forces stream resource materialization pre-main) --
__global__ void k_warm() {}

// ---------------- side-stream copy: out[:, :, t!=15, :] = pf ----------------
__global__ void __launch_bounds__(256) k_copy15(const float4* __restrict__ src,
                                                float4* __restrict__ dst) {
    int t  = threadIdx.x;
    int tt = blockIdx.y;          // 0..14
    int rb = blockIdx.x;          // 0..63
    #pragma unroll 4
    for (int j = t; j < 64*128; j += 256) {
        int k = j >> 7, w = j & 127;
        size_t idx = ((size_t)(rb*64 + k)*16 + tt) * 128 + w;
        dst[idx] = src[idx];
    }
}

// ---------------- graph aggregation (adjacency fused) ----------------
__global__ void __launch_bounds__(256) k_agg(const float* __restrict__ pf,
                                             const float* __restrict__ bbx, int mode) {
    __shared__ float Asm[NN*NN];
    __shared__ float Xs[NN][68];
    __shared__ float cx[NN], cy[NN], invdeg[NN];
    int b = blockIdx.x;
    int cBase = blockIdx.y * 64;
    int t = threadIdx.x;

    if (t < NN) {
        const float* p = bbx + (b*NN + t)*4;
        cx[t] = p[0] + 0.5f*p[2];
        cy[t] = p[1] + 0.5f*p[3];
    }
    __syncthreads();
    if (t < NN) {
        float x0 = cx[t], y0 = cy[t];
        int cnt = 0;
        #pragma unroll 8
        for (int m = 0; m < NN; m++) {
            float dx = x0 - cx[m], dy = y0 - cy[m];
            if (m != t && dx*dx + dy*dy < THR2) cnt++;
        }
        invdeg[t] = 1.0f / ((float)(cnt + 1) + 1e-6f);
    }
    __syncthreads();
    #pragma unroll
    for (int i = 0; i < 16; i++) {
        int e = t + 256*i;
        int m = e >> 6, n = e & 63;
        float dx = cx[n]-cx[m], dy = cy[n]-cy[m];
        float d2 = dx*dx + dy*dy;
        Asm[e] = (n == m || d2 < THR2) ? invdeg[n] : 0.0f;
    }
    #pragma unroll
    for (int i = 0; i < 4; i++) {
        int e  = t + 256*i;
        int n  = e >> 4;
        int cg = (e & 15) * 4;
        float4 v;
        if (mode == 0) {
            v = *(const float4*)&pf[((b*NN + n)*TT + 15)*DD + cBase + cg];
        } else {
            float4 z  = *(const float4*)&g_z[(b*NN + n)*DD + cBase + cg];
            float4 sc = *(const float4*)&g_scale[cBase + cg];
            float4 sh = *(const float4*)&g_shift[cBase + cg];
            v.x = fmaxf(fmaf(z.x, sc.x, sh.x), 0.0f);
            v.y = fmaxf(fmaf(z.y, sc.y, sh.y), 0.0f);
            v.z = fmaxf(fmaf(z.z, sc.z, sh.z), 0.0f);
            v.w = fmaxf(fmaf(z.w, sc.w, sh.w), 0.0f);
        }
        *(float4*)&Xs[n][cg] = v;
    }
    __syncthreads();

    int ty = t >> 4, tx = t & 15;
    int m0 = ty * 4, c0 = tx * 4;
    float acc[4][4] = {};
    for (int n = 0; n < NN; n++) {
        float a0 = Asm[(m0+0)*NN + n];
        float a1 = Asm[(m0+1)*NN + n];
        float a2 = Asm[(m0+2)*NN + n];
        float a3 = Asm[(m0+3)*NN + n];
        float4 xv = *(const float4*)&Xs[n][c0];
        acc[0][0] += a0*xv.x; acc[0][1] += a0*xv.y; acc[0][2] += a0*xv.z; acc[0][3] += a0*xv.w;
        acc[1][0] += a1*xv.x; acc[1][1] += a1*xv.y; acc[1][2] += a1*xv.z; acc[1][3] += a1*xv.w;
        acc[2][0] += a2*xv.x; acc[2][1] += a2*xv.y; acc[2][2] += a2*xv.z; acc[2][3] += a2*xv.w;
        acc[3][0] += a3*xv.x; acc[3][1] += a3*xv.y; acc[3][2] += a3*xv.z; acc[3][3] += a3*xv.w;
    }
    #pragma unroll
    for (int i = 0; i < 4; i++) {
        float4 v = make_float4(acc[i][0], acc[i][1], acc[i][2], acc[i][3]);
        *(float4*)&g_agg[(b*NN + m0 + i)*DD + cBase + c0] = v;
    }
}

// ---------------- tf32 mma.sync GEMM + fused BN partial stats ----------------
// g_z[r][o] = sum_c g_agg[r][c]*W[o][c] + bias[o]
// Block 64x128, BK=32, 8 warps (2M x 4N), warp tile 32x32 via m16n8k8.
// Smem: plain K-major, stride 36 floats (32 data + 4 pad), double-buffered,
// filled with cp.async (LDGSTS) so loads overlap HMMAs without register staging.
#define LDK 36
#define ABUF(b) ((b)*2304)
#define BBUF(b) (4608 + (b)*4608)
#define GEMM_SMEM (13824*4)     // 54KB

__device__ __forceinline__ void mma_tf32(float* c, const uint32_t* a, const uint32_t* b) {
    asm volatile(
        "mma.sync.aligned.m16n8k8.row.col.f32.tf32.tf32.f32 "
        "{%0,%1,%2,%3}, {%4,%5,%6,%7}, {%8,%9}, {%0,%1,%2,%3};"
        : "+f"(c[0]), "+f"(c[1]), "+f"(c[2]), "+f"(c[3])
        : "r"(a[0]), "r"(a[1]), "r"(a[2]), "r"(a[3]), "r"(b[0]), "r"(b[1]));
}
__device__ __forceinline__ void cp16(uint32_t dst, const void* src) {
    asm volatile("cp.async.ca.shared.global [%0], [%1], 16;" :: "r"(dst), "l"(src));
}
#define CP_COMMIT() asm volatile("cp.async.commit_group;" ::: "memory")
#define CP_WAIT0()  asm volatile("cp.async.wait_group 0;" ::: "memory")

__global__ void __launch_bounds__(256, 3) k_gemm_mma(const float* __restrict__ W,
                                                     const float* __restrict__ bias) {
    extern __shared__ float sm[];
    uint32_t sbase = (uint32_t)__cvta_generic_to_shared(sm);
    int t = threadIdx.x;
    int lane = t & 31;
    int wid = t >> 5;
    int wm = wid >> 2, wn = wid & 3;          // warp: 32-row half, 32-col quarter
    int rBase = blockIdx.x * 64;
    int oBase = blockIdx.y * 128;
    const float* A = g_agg;

    // fill indexing: each thread owns (row = t>>3, cg = (t&7)*4) (+32-row stride)
    int frow = t >> 3, fcg = (t & 7) * 4;

    // fragment base offsets (floats) within a buffer
    int aBase = (wm*32 + (lane >> 2))*LDK + (lane & 3);
    int bBase = (wn*32 + (lane >> 2))*LDK + (lane & 3);

    float acc[2][4][4];
    #pragma unroll
    for (int mt = 0; mt < 2; mt++)
        #pragma unroll
        for (int nt = 0; nt < 4; nt++)
            #pragma unroll
            for (int j = 0; j < 4; j++) acc[mt][nt][j] = 0.0f;

    // ---- async-fill chunk 0 into buffer 0 ----
    {
        #pragma unroll
        for (int i = 0; i < 2; i++) {
            int row = frow + 32*i;
            cp16(sbase + (ABUF(0) + row*LDK + fcg)*4, &A[(rBase+row)*DD + fcg]);
        }
        #pragma unroll
        for (int i = 0; i < 4; i++) {
            int row = frow + 32*i;
            cp16(sbase + (BBUF(0) + row*LDK + fcg)*4, &W[(oBase+row)*DD + fcg]);
        }
        CP_COMMIT();
        CP_WAIT0();
        __syncthreads();
    }

    #pragma unroll 1
    for (int it = 0; it < 16; it++) {
        int cur = it & 1;
        if (it + 1 < 16) {   // issue async fills for next chunk (overlap with HMMAs)
            int nb = 1 - cur;
            int k0 = (it + 1) * 32;
            #pragma unroll
            for (int i = 0; i < 2; i++) {
                int row = frow + 32*i;
                cp16(sbase + (ABUF(nb) + row*LDK + fcg)*4, &A[(rBase+row)*DD + k0 + fcg]);
            }
            #pragma unroll
            for (int i = 0; i < 4; i++) {
                int row = frow + 32*i;
                cp16(sbase + (BBUF(nb) + row*LDK + fcg)*4, &W[(oBase+row)*DD + k0 + fcg]);
            }
            CP_COMMIT();
        }
        // ---- compute on current buffer ----
        const float* as = &sm[ABUF(cur) + aBase];
        const float* bs = &sm[BBUF(cur) + bBase];
        #pragma unroll
        for (int ks = 0; ks < 4; ks++) {
            uint32_t af[2][4], bf[4][2];
            #pragma unroll
            for (int mt = 0; mt < 2; mt++) {
                #pragma unroll
                for (int j = 0; j < 4; j++)
                    af[mt][j] = __float_as_uint(as[(mt*16 + 8*(j&1))*LDK + ks*8 + 4*(j>>1)]);
            }
            #pragma unroll
            for (int nt = 0; nt < 4; nt++) {
                #pragma unroll
                for (int j = 0; j < 2; j++)
                    bf[nt][j] = __float_as_uint(bs[(nt*8)*LDK + ks*8 + 4*j]);
            }
            #pragma unroll
            for (int mt = 0; mt < 2; mt++)
                #pragma unroll
                for (int nt = 0; nt < 4; nt++)
                    mma_tf32(acc[mt][nt], af[mt], bf[nt]);
        }
        if (it + 1 < 16) CP_WAIT0();
        __syncthreads();
    }

    // ---- epilogue: bias add, write g_z, accumulate per-column stats ----
    float s[4][2], q[4][2];
    #pragma unroll
    for (int nt = 0; nt < 4; nt++) { s[nt][0]=s[nt][1]=q[nt][0]=q[nt][1]=0.0f; }

    #pragma unroll
    for (int nt = 0; nt < 4; nt++) {
        int col = oBase + wn*32 + nt*8 + (lane & 3)*2;
        float2 bv = *(const float2*)&bias[col];
        #pragma unroll
        for (int mt = 0; mt < 2; mt++) {
            int row0 = rBase + wm*32 + mt*16 + (lane >> 2);
            float2 v0 = make_float2(acc[mt][nt][0] + bv.x, acc[mt][nt][1] + bv.y);
            float2 v1 = make_float2(acc[mt][nt][2] + bv.x, acc[mt][nt][3] + bv.y);
            *(float2*)&g_z[row0*DD + col]     = v0;
            *(float2*)&g_z[(row0+8)*DD + col] = v1;
            s[nt][0] += v0.x + v1.x;  s[nt][1] += v0.y + v1.y;
            q[nt][0] += v0.x*v0.x + v1.x*v1.x;
            q[nt][1] += v0.y*v0.y + v1.y*v1.y;
        }
    }
    #pragma unroll
    for (int off = 4; off < 32; off <<= 1) {
        #pragma unroll
        for (int nt = 0; nt < 4; nt++) {
            s[nt][0] += __shfl_xor_sync(0xffffffffu, s[nt][0], off);
            s[nt][1] += __shfl_xor_sync(0xffffffffu, s[nt][1], off);
            q[nt][0] += __shfl_xor_sync(0xffffffffu, q[nt][0], off);
            q[nt][1] += __shfl_xor_sync(0xffffffffu, q[nt][1], off);
        }
    }
    float* red = sm;
    __syncthreads();
    if (lane < 4) {
        #pragma unroll
        for (int nt = 0; nt < 4; nt++) {
            int coll = wn*32 + nt*8 + lane*2;
            red[wm*256 +       coll    ] = s[nt][0];
            red[wm*256 +       coll + 1] = s[nt][1];
            red[wm*256 + 128 + coll    ] = q[nt][0];
            red[wm*256 + 128 + coll + 1] = q[nt][1];
        }
    }
    __syncthreads();
    if (t < 128) {
        float st = red[t]       + red[256 + t];
        float qt = red[128 + t] + red[384 + t];
        g_psum[blockIdx.x*DD + oBase + t] = st;
        g_psq [blockIdx.x*DD + oBase + t] = qt;
    }
}

// ---------------- BN finalize ----------------
__global__ void k_finalize(const float* __restrict__ gma, const float* __restrict__ bta) {
    int o = threadIdx.x;
    float s = 0.0f, q = 0.0f;
    #pragma unroll 8
    for (int i = 0; i < 64; i++) { s += g_psum[i*DD + o]; q += g_psq[i*DD + o]; }
    float mean = s * (1.0f/4096.0f);
    float var  = q * (1.0f/4096.0f) - mean*mean;
    float inv  = rsqrtf(var + 1e-5f);
    float sc   = gma[o] * inv;
    g_scale[o] = sc;
    g_shift[o] = bta[o] - mean * sc;
}

// ---------------- BN apply + ReLU -> out[:, :, 15, :] ----------------
__global__ void k_apply(float* __restrict__ outp) {
    int i  = blockIdx.x * blockDim.x + threadIdx.x;
    int r  = i >> 7;
    int cw = i & 127;
    float4 z  = ((const float4*)g_z)[i];
    float4 sc = ((const float4*)g_scale)[cw];
    float4 sh = ((const float4*)g_shift)[cw];
    float4 h;
    h.x = fmaxf(fmaf(z.x, sc.x, sh.x), 0.0f);
    h.y = fmaxf(fmaf(z.y, sc.y, sh.y), 0.0f);
    h.z = fmaxf(fmaf(z.z, sc.z, sh.z), 0.0f);
    h.w = fmaxf(fmaf(z.w, sc.w, sh.w), 0.0f);
    *(float4*)&outp[r*(TT*DD) + 15*DD + cw*4] = h;
}

// ---------------- side stream + events (created pre-main, no allocs in launch) --
namespace {
struct SideStream {
    cudaStream_t s;
    cudaEvent_t evFork, evJoin;
    SideStream() {
        cudaStreamCreateWithFlags(&s, cudaStreamNonBlocking);
        cudaEventCreateWithFlags(&evFork, cudaEventDisableTiming);
        cudaEventCreateWithFlags(&evJoin, cudaEventDisableTiming);
        k_warm<<<1, 32, 0, s>>>();
        cudaStreamSynchronize(s);
    }
};
SideStream g_ss;
}

// ---------------- launcher ----------------
extern "C" void kernel_launch(void* const* d_in, const int* in_sizes, int n_in,
                              void* d_out, int out_size) {
    const float* pf  = (const float*)d_in[0];
    const float* bbx = (const float*)d_in[1];
    const float* w1  = (const float*)d_in[2];
    const float* b1  = (const float*)d_in[3];
    const float* g1  = (const float*)d_in[4];
    const float* be1 = (const float*)d_in[5];
    const float* w2  = (const float*)d_in[6];
    const float* b2  = (const float*)d_in[7];
    const float* g2  = (const float*)d_in[8];
    const float* be2 = (const float*)d_in[9];
    float* out = (float*)d_out;

    static int s_attr_done = 0;
    if (!s_attr_done) {
        cudaFuncSetAttribute(k_gemm_mma, cudaFuncAttributeMaxDynamicSharedMemorySize, GEMM_SMEM);
        s_attr_done = 1;
    }

    // fork: bulk copy of t=0..14 slices runs concurrently on the side stream
    cudaEventRecord(g_ss.evFork, 0);
    cudaStreamWaitEvent(g_ss.s, g_ss.evFork, 0);
    k_copy15<<<dim3(64, 15), 256, 0, g_ss.s>>>((const float4*)pf, (float4*)out);
    cudaEventRecord(g_ss.evJoin, g_ss.s);

    // layer 1
    k_agg<<<dim3(64, 8), 256>>>(pf, bbx, 0);
    k_gemm_mma<<<dim3(64, 4), 256, GEMM_SMEM>>>(w1, b1);
    k_finalize<<<1, 512>>>(g1, be1);

    // layer 2 (BN-apply of layer 1 fused into the aggregation load)
    k_agg<<<dim3(64, 8), 256>>>(nullptr, bbx, 1);
    k_gemm_mma<<<dim3(64, 4), 256, GEMM_SMEM>>>(w2, b2);
    k_finalize<<<1, 512>>>(g2, be2);
    k_apply<<<2048, 256>>>(out);

    // join side stream before the graph/launch completes
    cudaStreamWaitEvent(0, g_ss.evJoin, 0);
}